// round 15
// baseline (speedup 1.0000x reference)
#include <cuda_runtime.h>

#define NUM_NODES 1000000
#define NUM_EDGES 16000000
#define F  6
#define FP 8   // padded feature width: 32B row = one L2 sector

// Scratch: device globals (no allocation allowed anywhere).
__device__ __align__(128) float g_x8 [NUM_NODES * FP];  // padded x (lanes 6,7 = 0)
__device__ __align__(128) float g_agg[NUM_NODES * FP];  // scatter-add accumulator
__device__ __align__(128) float g_h8 [NUM_NODES * FP];  // padded layer-1 output
__device__ int g_idx_is32;                              // 1 if edge_index is int32

// ---------------------------------------------------------------------------
// prep: pad x into g_x8 (2 nodes/thread, vectorized 3x float4 reads), zero
// g_agg. Block 0 additionally detects the edge-index dtype.
// ---------------------------------------------------------------------------
__global__ void prep_kernel(const float* __restrict__ x,
                            const long long* __restrict__ ei) {
    if (blockIdx.x == 0) {
        __shared__ int bad;
        if (threadIdx.x == 0) bad = 0;
        __syncthreads();
        #pragma unroll
        for (int r = 0; r < 16; r++) {
            long long v = ei[threadIdx.x + r * 256];
            if ((unsigned long long)v >= (unsigned long long)NUM_NODES) bad = 1;
        }
        __syncthreads();
        if (threadIdx.x == 0) g_idx_is32 = bad;
    }
    int i = blockIdx.x * blockDim.x + threadIdx.x;    // node-pair id
    if (i >= NUM_NODES / 2) return;
    const float4* px = reinterpret_cast<const float4*>(x + (size_t)i * 12);
    float4 a = __ldcs(px);                             // x[2i][0..3]
    float4 bq = __ldcs(px + 1);                        // x[2i][4,5], x[2i+1][0,1]
    float4 c = __ldcs(px + 2);                         // x[2i+1][2..5]

    float4* po = reinterpret_cast<float4*>(g_x8 + (size_t)i * 2 * FP);
    po[0] = a;
    po[1] = make_float4(bq.x, bq.y, 0.f, 0.f);
    po[2] = make_float4(bq.z, bq.w, c.x, c.y);
    po[3] = make_float4(c.z, c.w, 0.f, 0.f);

    float4 z = make_float4(0.f, 0.f, 0.f, 0.f);
    float4* pa = reinterpret_cast<float4*>(g_agg + (size_t)i * 2 * FP);
    pa[0] = z; pa[1] = z; pa[2] = z; pa[3] = z;
}

__device__ __forceinline__ void red_add_v4(float* p, float4 v) {
    asm volatile("red.global.add.v4.f32 [%0], {%1, %2, %3, %4};"
                 :: "l"(p), "f"(v.x), "f"(v.y), "f"(v.z), "f"(v.w) : "memory");
}

// ---------------------------------------------------------------------------
// Lane-paired edge scatter (champion config: 169.9us/layer, ~96% of the
// structural floor). Work item = half-edge (item = 2e + h). Even lane of a
// pair loads src[e], odd loads dst[e]; 2 shfls share both. Each lane loads
// 16B half h of the source row (pair shares one 128B line -> 1 gather
// wavefront/edge; evict-first since L1 hit rate on a 32MB random table is
// ~0.7%) and REDs into half h of the accumulator row.
// ---------------------------------------------------------------------------
#define NITEMS (2 * NUM_EDGES)
#define ITEMS_PER_THREAD 4
#define SCAT_THREADS (NITEMS / ITEMS_PER_THREAD)   // 8M (exact multiple of 256)

template <int PHASE>
__global__ void scatter_kernel(const void* __restrict__ ei) {
    int gid = blockIdx.x * blockDim.x + threadIdx.x;
    const float* feat = (PHASE == 0) ? g_x8 : g_h8;
    const bool is32 = (g_idx_is32 != 0);
    const int lane = threadIdx.x & 31;
    const int h    = gid & 1;                         // fixed half per thread

    unsigned s[ITEMS_PER_THREAD], d[ITEMS_PER_THREAD];
    #pragma unroll
    for (int k = 0; k < ITEMS_PER_THREAD; k++) {
        int item = gid + k * SCAT_THREADS;            // parity preserved
        int e = item >> 1;                            // same e for both pair lanes
        unsigned my;
        if (is32) {
            const int* p = (h == 0) ? (const int*)ei
                                    : (const int*)ei + NUM_EDGES;
            my = (unsigned)__ldcs(p + e);
        } else {
            const long long* p = (h == 0) ? (const long long*)ei
                                          : (const long long*)ei + NUM_EDGES;
            my = (unsigned)__ldcs(p + e);
        }
        s[k] = __shfl_sync(0xFFFFFFFFu, my, lane & ~1);   // src from even lane
        d[k] = __shfl_sync(0xFFFFFFFFu, my, lane |  1);   // dst from odd lane
    }

    float4 v[ITEMS_PER_THREAD];
    bool ok[ITEMS_PER_THREAD];
    #pragma unroll
    for (int k = 0; k < ITEMS_PER_THREAD; k++) {
        ok[k] = (s[k] < NUM_NODES) && (d[k] < NUM_NODES);
        if (ok[k])
            v[k] = __ldcs(reinterpret_cast<const float4*>(feat + (size_t)s[k] * FP) + h);
    }
    #pragma unroll
    for (int k = 0; k < ITEMS_PER_THREAD; k++) {
        if (ok[k])
            red_add_v4(g_agg + (size_t)d[k] * FP + h * 4, v[k]);
    }
}

// ---------------------------------------------------------------------------
// per-node dense transform (champion R12 form: 1 node/thread).
// FINAL=false : write padded h into g_h8, re-zero g_agg for layer 2.
// FINAL=true  : argmax (first-max wins = jnp.argmax) -> one-hot (streaming).
// ---------------------------------------------------------------------------
template <bool FINAL>
__global__ void transform_kernel(const float* __restrict__ Wrel,
                                 const float* __restrict__ Wroot,
                                 const float* __restrict__ b,
                                 float* __restrict__ out) {
    __shared__ float swr[36], swo[36], sb[6];
    int t = threadIdx.x;
    if (t < 36)        swr[t]      = Wrel[t];
    else if (t < 72)   swo[t - 36] = Wroot[t - 36];
    else if (t < 78)   sb[t - 72]  = b[t - 72];
    __syncthreads();

    int i = blockIdx.x * blockDim.x + t;
    if (i >= NUM_NODES) return;

    const float* in_feat = FINAL ? g_h8 : g_x8;

    const float4* pa = reinterpret_cast<const float4*>(g_agg + (size_t)i * FP);
    float4 a0 = __ldcs(pa);     float4 a1 = __ldcs(pa + 1);
    const float4* px = reinterpret_cast<const float4*>(in_feat + (size_t)i * FP);
    float4 x0 = __ldcs(px);     float4 x1 = __ldcs(px + 1);

    float ag[6] = {a0.x, a0.y, a0.z, a0.w, a1.x, a1.y};
    float xv[6] = {x0.x, x0.y, x0.z, x0.w, x1.x, x1.y};

    float h[6];
    #pragma unroll
    for (int k = 0; k < 6; k++) {
        float acc = sb[k];
        #pragma unroll
        for (int j = 0; j < 6; j++) {
            acc = fmaf(ag[j], swr[k * 6 + j], acc);
            acc = fmaf(xv[j], swo[k * 6 + j], acc);
        }
        h[k] = acc;
    }

    if (!FINAL) {
        float4 z = make_float4(0.f, 0.f, 0.f, 0.f);
        float4* paw = reinterpret_cast<float4*>(g_agg + (size_t)i * FP);
        paw[0] = z; paw[1] = z;
        float4* ph = reinterpret_cast<float4*>(g_h8 + (size_t)i * FP);
        ph[0] = make_float4(h[0], h[1], h[2], h[3]);
        ph[1] = make_float4(h[4], h[5], 0.f, 0.f);
    } else {
        int best = 0; float bv = h[0];
        #pragma unroll
        for (int k = 1; k < 6; k++)
            if (h[k] > bv) { bv = h[k]; best = k; }
        // streaming scalar stores: output is never re-read on-device
        float* po = out + (size_t)i * F;
        #pragma unroll
        for (int k = 0; k < 6; k++) {
            float val = (k == best) ? 1.f : 0.f;
            asm volatile("st.global.cs.f32 [%0], %1;" :: "l"(po + k), "f"(val) : "memory");
        }
    }
}

extern "C" void kernel_launch(void* const* d_in, const int* in_sizes, int n_in,
                              void* d_out, int out_size) {
    const float* x      = (const float*)d_in[0];
    const void*  ei     = d_in[1];
    const float* Wrel1  = (const float*)d_in[2];
    const float* Wroot1 = (const float*)d_in[3];
    const float* b1     = (const float*)d_in[4];
    const float* Wrel2  = (const float*)d_in[5];
    const float* Wroot2 = (const float*)d_in[6];
    const float* b2     = (const float*)d_in[7];
    float*       out    = (float*)d_out;

    const int BLK = 256;
    const int node_grid = (NUM_NODES + BLK - 1) / BLK;
    const int pair_grid = (NUM_NODES / 2 + BLK - 1) / BLK;
    const int scat_grid = SCAT_THREADS / BLK;          // exact (31250)

    // Layer 1
    prep_kernel<<<pair_grid, BLK>>>(x, (const long long*)ei);
    scatter_kernel<0><<<scat_grid, BLK>>>(ei);
    transform_kernel<false><<<node_grid, BLK>>>(Wrel1, Wroot1, b1, nullptr);
    // Layer 2
    scatter_kernel<1><<<scat_grid, BLK>>>(ei);
    transform_kernel<true><<<node_grid, BLK>>>(Wrel2, Wroot2, b2, out);
}

// round 16
// speedup vs baseline: 1.0567x; 1.0567x over previous
#include <cuda_runtime.h>

#define NUM_NODES 1000000
#define NUM_EDGES 16000000
#define F  6
#define FP 8   // padded feature width: 32B row = one L2 sector

// Scratch: device globals (no allocation allowed anywhere).
__device__ __align__(128) float g_x8 [NUM_NODES * FP];  // padded x (lanes 6,7 = 0)
__device__ __align__(128) float g_agg[NUM_NODES * FP];  // scatter-add accumulator
__device__ __align__(128) float g_h8 [NUM_NODES * FP];  // padded layer-1 output
__device__ int g_idx_is32;                              // 1 if edge_index is int32

// ---------------------------------------------------------------------------
// prep: pad x into g_x8 (2 nodes/thread, vectorized 3x float4 reads), zero
// g_agg. Block 0 additionally detects the edge-index dtype.
// ---------------------------------------------------------------------------
__global__ void prep_kernel(const float* __restrict__ x,
                            const long long* __restrict__ ei) {
    if (blockIdx.x == 0) {
        __shared__ int bad;
        if (threadIdx.x == 0) bad = 0;
        __syncthreads();
        #pragma unroll
        for (int r = 0; r < 16; r++) {
            long long v = ei[threadIdx.x + r * 256];
            if ((unsigned long long)v >= (unsigned long long)NUM_NODES) bad = 1;
        }
        __syncthreads();
        if (threadIdx.x == 0) g_idx_is32 = bad;
    }
    int i = blockIdx.x * blockDim.x + threadIdx.x;    // node-pair id
    if (i >= NUM_NODES / 2) return;
    const float4* px = reinterpret_cast<const float4*>(x + (size_t)i * 12);
    float4 a = __ldcs(px);                             // x[2i][0..3]  (single-touch stream: .cs OK)
    float4 bq = __ldcs(px + 1);                        // x[2i][4,5], x[2i+1][0,1]
    float4 c = __ldcs(px + 2);                         // x[2i+1][2..5]

    float4* po = reinterpret_cast<float4*>(g_x8 + (size_t)i * 2 * FP);
    po[0] = a;
    po[1] = make_float4(bq.x, bq.y, 0.f, 0.f);
    po[2] = make_float4(bq.z, bq.w, c.x, c.y);
    po[3] = make_float4(c.z, c.w, 0.f, 0.f);

    float4 z = make_float4(0.f, 0.f, 0.f, 0.f);
    float4* pa = reinterpret_cast<float4*>(g_agg + (size_t)i * 2 * FP);
    pa[0] = z; pa[1] = z; pa[2] = z; pa[3] = z;
}

__device__ __forceinline__ void red_add_v4(float* p, float4 v) {
    asm volatile("red.global.add.v4.f32 [%0], {%1, %2, %3, %4};"
                 :: "l"(p), "f"(v.x), "f"(v.y), "f"(v.z), "f"(v.w) : "memory");
}

// ---------------------------------------------------------------------------
// Lane-paired edge scatter (champion: 169.9us/layer, ~96% of the structural
// floor). Work item = half-edge (item = 2e + h). Even lane of a pair loads
// src[e], odd loads dst[e]; 2 shfls share both. Each lane loads 16B half h
// of the source row with DEFAULT cache policy (the 32MB table is ~16x
// re-referenced per layer and lives in L2; .cs here doubles DRAM traffic —
// measured R15) and REDs into half h of the accumulator row. Index streams
// ARE single-touch -> .cs on those only.
// ---------------------------------------------------------------------------
#define NITEMS (2 * NUM_EDGES)
#define ITEMS_PER_THREAD 4
#define SCAT_THREADS (NITEMS / ITEMS_PER_THREAD)   // 8M (exact multiple of 256)

template <int PHASE>
__global__ void scatter_kernel(const void* __restrict__ ei) {
    int gid = blockIdx.x * blockDim.x + threadIdx.x;
    const float* feat = (PHASE == 0) ? g_x8 : g_h8;
    const bool is32 = (g_idx_is32 != 0);
    const int lane = threadIdx.x & 31;
    const int h    = gid & 1;                         // fixed half per thread

    unsigned s[ITEMS_PER_THREAD], d[ITEMS_PER_THREAD];
    #pragma unroll
    for (int k = 0; k < ITEMS_PER_THREAD; k++) {
        int item = gid + k * SCAT_THREADS;            // parity preserved
        int e = item >> 1;                            // same e for both pair lanes
        unsigned my;
        if (is32) {
            const int* p = (h == 0) ? (const int*)ei
                                    : (const int*)ei + NUM_EDGES;
            my = (unsigned)__ldcs(p + e);
        } else {
            const long long* p = (h == 0) ? (const long long*)ei
                                          : (const long long*)ei + NUM_EDGES;
            my = (unsigned)__ldcs(p + e);
        }
        s[k] = __shfl_sync(0xFFFFFFFFu, my, lane & ~1);   // src from even lane
        d[k] = __shfl_sync(0xFFFFFFFFu, my, lane |  1);   // dst from odd lane
    }

    float4 v[ITEMS_PER_THREAD];
    bool ok[ITEMS_PER_THREAD];
    #pragma unroll
    for (int k = 0; k < ITEMS_PER_THREAD; k++) {
        ok[k] = (s[k] < NUM_NODES) && (d[k] < NUM_NODES);
        if (ok[k])
            v[k] = *(reinterpret_cast<const float4*>(feat + (size_t)s[k] * FP) + h);
    }
    #pragma unroll
    for (int k = 0; k < ITEMS_PER_THREAD; k++) {
        if (ok[k])
            red_add_v4(g_agg + (size_t)d[k] * FP + h * 4, v[k]);
    }
}

// ---------------------------------------------------------------------------
// per-node dense transform (champion R12 form: 1 node/thread).
// FINAL=false : write padded h into g_h8, re-zero g_agg for layer 2.
// FINAL=true  : argmax (first-max wins = jnp.argmax) -> one-hot (streaming).
// ---------------------------------------------------------------------------
template <bool FINAL>
__global__ void transform_kernel(const float* __restrict__ Wrel,
                                 const float* __restrict__ Wroot,
                                 const float* __restrict__ b,
                                 float* __restrict__ out) {
    __shared__ float swr[36], swo[36], sb[6];
    int t = threadIdx.x;
    if (t < 36)        swr[t]      = Wrel[t];
    else if (t < 72)   swo[t - 36] = Wroot[t - 36];
    else if (t < 78)   sb[t - 72]  = b[t - 72];
    __syncthreads();

    int i = blockIdx.x * blockDim.x + t;
    if (i >= NUM_NODES) return;

    const float* in_feat = FINAL ? g_h8 : g_x8;

    // .cs here is safe: each agg/x8/h8 row is read exactly once by this
    // kernel and (for agg) rewritten before any other reader.
    const float4* pa = reinterpret_cast<const float4*>(g_agg + (size_t)i * FP);
    float4 a0 = __ldcs(pa);     float4 a1 = __ldcs(pa + 1);
    const float4* px = reinterpret_cast<const float4*>(in_feat + (size_t)i * FP);
    float4 x0 = __ldcs(px);     float4 x1 = __ldcs(px + 1);

    float ag[6] = {a0.x, a0.y, a0.z, a0.w, a1.x, a1.y};
    float xv[6] = {x0.x, x0.y, x0.z, x0.w, x1.x, x1.y};

    float h[6];
    #pragma unroll
    for (int k = 0; k < 6; k++) {
        float acc = sb[k];
        #pragma unroll
        for (int j = 0; j < 6; j++) {
            acc = fmaf(ag[j], swr[k * 6 + j], acc);
            acc = fmaf(xv[j], swo[k * 6 + j], acc);
        }
        h[k] = acc;
    }

    if (!FINAL) {
        float4 z = make_float4(0.f, 0.f, 0.f, 0.f);
        float4* paw = reinterpret_cast<float4*>(g_agg + (size_t)i * FP);
        paw[0] = z; paw[1] = z;
        float4* ph = reinterpret_cast<float4*>(g_h8 + (size_t)i * FP);
        ph[0] = make_float4(h[0], h[1], h[2], h[3]);
        ph[1] = make_float4(h[4], h[5], 0.f, 0.f);
    } else {
        int best = 0; float bv = h[0];
        #pragma unroll
        for (int k = 1; k < 6; k++)
            if (h[k] > bv) { bv = h[k]; best = k; }
        // streaming scalar stores: output is never re-read on-device
        float* po = out + (size_t)i * F;
        #pragma unroll
        for (int k = 0; k < 6; k++) {
            float val = (k == best) ? 1.f : 0.f;
            asm volatile("st.global.cs.f32 [%0], %1;" :: "l"(po + k), "f"(val) : "memory");
        }
    }
}

extern "C" void kernel_launch(void* const* d_in, const int* in_sizes, int n_in,
                              void* d_out, int out_size) {
    const float* x      = (const float*)d_in[0];
    const void*  ei     = d_in[1];
    const float* Wrel1  = (const float*)d_in[2];
    const float* Wroot1 = (const float*)d_in[3];
    const float* b1     = (const float*)d_in[4];
    const float* Wrel2  = (const float*)d_in[5];
    const float* Wroot2 = (const float*)d_in[6];
    const float* b2     = (const float*)d_in[7];
    float*       out    = (float*)d_out;

    const int BLK = 256;
    const int node_grid = (NUM_NODES + BLK - 1) / BLK;
    const int pair_grid = (NUM_NODES / 2 + BLK - 1) / BLK;
    const int scat_grid = SCAT_THREADS / BLK;          // exact (31250)

    // Layer 1
    prep_kernel<<<pair_grid, BLK>>>(x, (const long long*)ei);
    scatter_kernel<0><<<scat_grid, BLK>>>(ei);
    transform_kernel<false><<<node_grid, BLK>>>(Wrel1, Wroot1, b1, nullptr);
    // Layer 2
    scatter_kernel<1><<<scat_grid, BLK>>>(ei);
    transform_kernel<true><<<node_grid, BLK>>>(Wrel2, Wroot2, b2, out);
}

// round 17
// speedup vs baseline: 1.0581x; 1.0013x over previous
#include <cuda_runtime.h>

#define NUM_NODES 1000000
#define NUM_EDGES 16000000
#define F  6
#define FP 8   // padded feature width: 32B row = one L2 sector

// Scratch: device globals (no allocation allowed anywhere).
__device__ __align__(128) float g_x8 [NUM_NODES * FP];  // padded x (lanes 6,7 = 0)
__device__ __align__(128) float g_agg[NUM_NODES * FP];  // scatter-add accumulator
__device__ __align__(128) float g_h8 [NUM_NODES * FP];  // padded layer-1 output
__device__ int g_idx_is32;                              // 1 if edge_index is int32

// PDL: wait for the previous grid's memory to be visible (no-op if the
// kernel was launched without the PDL attribute).
__device__ __forceinline__ void pdl_wait() {
    asm volatile("griddepcontrol.wait;" ::: "memory");
}

// ---------------------------------------------------------------------------
// prep: pad x into g_x8 (2 nodes/thread, vectorized 3x float4 reads), zero
// g_agg. Block 0 additionally detects the edge-index dtype. First kernel:
// launched normally (no predecessor).
// ---------------------------------------------------------------------------
__global__ void prep_kernel(const float* __restrict__ x,
                            const long long* __restrict__ ei) {
    if (blockIdx.x == 0) {
        __shared__ int bad;
        if (threadIdx.x == 0) bad = 0;
        __syncthreads();
        #pragma unroll
        for (int r = 0; r < 16; r++) {
            long long v = ei[threadIdx.x + r * 256];
            if ((unsigned long long)v >= (unsigned long long)NUM_NODES) bad = 1;
        }
        __syncthreads();
        if (threadIdx.x == 0) g_idx_is32 = bad;
    }
    int i = blockIdx.x * blockDim.x + threadIdx.x;    // node-pair id
    if (i >= NUM_NODES / 2) return;
    const float4* px = reinterpret_cast<const float4*>(x + (size_t)i * 12);
    float4 a = __ldcs(px);                             // single-touch stream: .cs OK
    float4 bq = __ldcs(px + 1);
    float4 c = __ldcs(px + 2);

    float4* po = reinterpret_cast<float4*>(g_x8 + (size_t)i * 2 * FP);
    po[0] = a;
    po[1] = make_float4(bq.x, bq.y, 0.f, 0.f);
    po[2] = make_float4(bq.z, bq.w, c.x, c.y);
    po[3] = make_float4(c.z, c.w, 0.f, 0.f);

    float4 z = make_float4(0.f, 0.f, 0.f, 0.f);
    float4* pa = reinterpret_cast<float4*>(g_agg + (size_t)i * 2 * FP);
    pa[0] = z; pa[1] = z; pa[2] = z; pa[3] = z;
}

__device__ __forceinline__ void red_add_v4(float* p, float4 v) {
    asm volatile("red.global.add.v4.f32 [%0], {%1, %2, %3, %4};"
                 :: "l"(p), "f"(v.x), "f"(v.y), "f"(v.z), "f"(v.w) : "memory");
}

// ---------------------------------------------------------------------------
// Lane-paired edge scatter (champion body: 168.8us/layer, ~96% of the
// structural floor). PDL: index loads + shfls touch only the immutable
// edge_index -> run BEFORE griddepcontrol.wait, overlapping the previous
// kernel's drain. Feature gathers / REDs (which need prep/transform output)
// run after the wait. g_idx_is32 is written by prep (2 kernels upstream of
// scatter<1>, 1 upstream of scatter<0>) — read it post-wait? No: for
// scatter<0> it is written by prep, the direct predecessor, so the flag
// read must ALSO be pre-guarded. We read it post-wait and do the index
// loads for BOTH dtypes' address math cheaply: addresses depend only on the
// flag via the base pointer, so we instead read the flag first thing after
// wait... Simplest correct scheme: wait FIRST in scatter<0>'s flag path.
// To keep real overlap, we hoist only the e/address arithmetic pre-wait and
// issue loads after the wait — the dominant win remains the early block
// dispatch + index-load issue of the first wave during predecessor tail.
// ---------------------------------------------------------------------------
#define NITEMS (2 * NUM_EDGES)
#define ITEMS_PER_THREAD 4
#define SCAT_THREADS (NITEMS / ITEMS_PER_THREAD)   // 8M (exact multiple of 256)

template <int PHASE>
__global__ void scatter_kernel(const void* __restrict__ ei) {
    int gid = blockIdx.x * blockDim.x + threadIdx.x;
    const float* feat = (PHASE == 0) ? g_x8 : g_h8;
    const int lane = threadIdx.x & 31;
    const int h    = gid & 1;                         // fixed half per thread

    // pre-wait: pure arithmetic (edge ids, parity) — no protected reads
    int e[ITEMS_PER_THREAD];
    #pragma unroll
    for (int k = 0; k < ITEMS_PER_THREAD; k++)
        e[k] = (gid + k * SCAT_THREADS) >> 1;

    // predecessor (prep / transform<0>) wrote g_idx_is32 / g_x8 / g_h8 / g_agg
    pdl_wait();

    const bool is32 = (g_idx_is32 != 0);
    unsigned s[ITEMS_PER_THREAD], d[ITEMS_PER_THREAD];
    #pragma unroll
    for (int k = 0; k < ITEMS_PER_THREAD; k++) {
        unsigned my;
        if (is32) {
            const int* p = (h == 0) ? (const int*)ei
                                    : (const int*)ei + NUM_EDGES;
            my = (unsigned)__ldcs(p + e[k]);
        } else {
            const long long* p = (h == 0) ? (const long long*)ei
                                          : (const long long*)ei + NUM_EDGES;
            my = (unsigned)__ldcs(p + e[k]);
        }
        s[k] = __shfl_sync(0xFFFFFFFFu, my, lane & ~1);   // src from even lane
        d[k] = __shfl_sync(0xFFFFFFFFu, my, lane |  1);   // dst from odd lane
    }

    float4 v[ITEMS_PER_THREAD];
    bool ok[ITEMS_PER_THREAD];
    #pragma unroll
    for (int k = 0; k < ITEMS_PER_THREAD; k++) {
        ok[k] = (s[k] < NUM_NODES) && (d[k] < NUM_NODES);
        if (ok[k])
            v[k] = *(reinterpret_cast<const float4*>(feat + (size_t)s[k] * FP) + h);
    }
    #pragma unroll
    for (int k = 0; k < ITEMS_PER_THREAD; k++) {
        if (ok[k])
            red_add_v4(g_agg + (size_t)d[k] * FP + h * 4, v[k]);
    }
}

// ---------------------------------------------------------------------------
// per-node dense transform (champion body). PDL: weight/bias smem staging
// runs pre-wait (inputs are immutable harness buffers); agg/feature reads
// run post-wait.
// FINAL=false : write padded h into g_h8, re-zero g_agg for layer 2.
// FINAL=true  : argmax (first-max wins = jnp.argmax) -> one-hot (streaming).
// ---------------------------------------------------------------------------
template <bool FINAL>
__global__ void transform_kernel(const float* __restrict__ Wrel,
                                 const float* __restrict__ Wroot,
                                 const float* __restrict__ b,
                                 float* __restrict__ out) {
    __shared__ float swr[36], swo[36], sb[6];
    int t = threadIdx.x;
    if (t < 36)        swr[t]      = Wrel[t];
    else if (t < 72)   swo[t - 36] = Wroot[t - 36];
    else if (t < 78)   sb[t - 72]  = b[t - 72];
    __syncthreads();

    // predecessor (scatter) REDs into g_agg must be visible
    pdl_wait();

    int i = blockIdx.x * blockDim.x + t;
    if (i >= NUM_NODES) return;

    const float* in_feat = FINAL ? g_h8 : g_x8;

    // .cs safe: each agg/x8/h8 row is read exactly once by this kernel and
    // (for agg) rewritten before any other reader.
    const float4* pa = reinterpret_cast<const float4*>(g_agg + (size_t)i * FP);
    float4 a0 = __ldcs(pa);     float4 a1 = __ldcs(pa + 1);
    const float4* px = reinterpret_cast<const float4*>(in_feat + (size_t)i * FP);
    float4 x0 = __ldcs(px);     float4 x1 = __ldcs(px + 1);

    float ag[6] = {a0.x, a0.y, a0.z, a0.w, a1.x, a1.y};
    float xv[6] = {x0.x, x0.y, x0.z, x0.w, x1.x, x1.y};

    float h[6];
    #pragma unroll
    for (int k = 0; k < 6; k++) {
        float acc = sb[k];
        #pragma unroll
        for (int j = 0; j < 6; j++) {
            acc = fmaf(ag[j], swr[k * 6 + j], acc);
            acc = fmaf(xv[j], swo[k * 6 + j], acc);
        }
        h[k] = acc;
    }

    if (!FINAL) {
        float4 z = make_float4(0.f, 0.f, 0.f, 0.f);
        float4* paw = reinterpret_cast<float4*>(g_agg + (size_t)i * FP);
        paw[0] = z; paw[1] = z;
        float4* ph = reinterpret_cast<float4*>(g_h8 + (size_t)i * FP);
        ph[0] = make_float4(h[0], h[1], h[2], h[3]);
        ph[1] = make_float4(h[4], h[5], 0.f, 0.f);
    } else {
        int best = 0; float bv = h[0];
        #pragma unroll
        for (int k = 1; k < 6; k++)
            if (h[k] > bv) { bv = h[k]; best = k; }
        float* po = out + (size_t)i * F;
        #pragma unroll
        for (int k = 0; k < 6; k++) {
            float val = (k == best) ? 1.f : 0.f;
            asm volatile("st.global.cs.f32 [%0], %1;" :: "l"(po + k), "f"(val) : "memory");
        }
    }
}

// Launch a kernel with the PDL attribute so its blocks may be dispatched
// (and run pre-wait work) while the predecessor grid drains.
template <typename... Args>
static void launch_pdl(void (*kern)(Args...), dim3 grid, dim3 blk,
                       Args... args) {
    cudaLaunchConfig_t cfg = {};
    cfg.gridDim = grid;
    cfg.blockDim = blk;
    cudaLaunchAttribute attr[1];
    attr[0].id = cudaLaunchAttributeProgrammaticStreamSerialization;
    attr[0].val.programmaticStreamSerializationAllowed = 1;
    cfg.attrs = attr;
    cfg.numAttrs = 1;
    cudaLaunchKernelEx(&cfg, kern, args...);
}

extern "C" void kernel_launch(void* const* d_in, const int* in_sizes, int n_in,
                              void* d_out, int out_size) {
    const float* x      = (const float*)d_in[0];
    const void*  ei     = d_in[1];
    const float* Wrel1  = (const float*)d_in[2];
    const float* Wroot1 = (const float*)d_in[3];
    const float* b1     = (const float*)d_in[4];
    const float* Wrel2  = (const float*)d_in[5];
    const float* Wroot2 = (const float*)d_in[6];
    const float* b2     = (const float*)d_in[7];
    float*       out    = (float*)d_out;

    const int BLK = 256;
    const int node_grid = (NUM_NODES + BLK - 1) / BLK;
    const int pair_grid = (NUM_NODES / 2 + BLK - 1) / BLK;
    const int scat_grid = SCAT_THREADS / BLK;          // exact (31250)

    // Layer 1
    prep_kernel<<<pair_grid, BLK>>>(x, (const long long*)ei);
    launch_pdl(scatter_kernel<0>, dim3(scat_grid), dim3(BLK), ei);
    launch_pdl(transform_kernel<false>, dim3(node_grid), dim3(BLK),
               Wrel1, Wroot1, b1, (float*)nullptr);
    // Layer 2
    launch_pdl(scatter_kernel<1>, dim3(scat_grid), dim3(BLK), ei);
    launch_pdl(transform_kernel<true>, dim3(node_grid), dim3(BLK),
               Wrel2, Wroot2, b2, out);
}